// round 16
// baseline (speedup 1.0000x reference)
#include <cuda_runtime.h>

#define NSER 8192
#define OBS 9
#define NBLK2 128             // CTAs (each runs BOTH time segments on 4 warps)
#define TPB 128               // warps 0,1 = segment A; warps 2,3 = segment B
#define CT 10                 // timesteps per staged chunk
#define ROWF (CT * OBS)       // 90 floats; 90 mod 32 = 26, gcd 2 -> 2-way conflicts
#define SEGBUF (64 * ROWF)    // floats per (segment, parity) buffer
#define LOG2PI_F 1.8378770664093453f

static __device__ double g_partials[NBLK2];
static __device__ unsigned int g_done = 0;

__device__ __forceinline__ unsigned su32(const void* p) {
    unsigned a;
    asm("{ .reg .u64 t; cvta.to.shared.u64 t, %1; cvt.u32.u64 %0, t; }"
        : "=r"(a) : "l"(p));
    return a;
}

// Time-split regime-switching KF. R15 profile showed 64-thread CTAs only occupy
// SMSPs 0/1 (wid%4), so 2-CTA SMs had 4 warps on 2 SMSPs with SMSPs 2/3 idle.
// Fix: 128 CTAs x 128 threads -> 1 CTA/SM, warps 0..3 on SMSPs 0..3, each warp
// alone on its SMSP. Warps 0,1: segment A (t [0,210), acc all). Warps 2,3:
// segment B (t [190,400), 20-step warmup, acc from t=210). Same 64 series per
// CTA in both segments. Step math byte-identical to R9..R15.
__global__ void __launch_bounds__(TPB) kf_kernel(
    float* __restrict__ out,
    const float* __restrict__ y,
    const float* __restrict__ B1s1_p,
    const float* __restrict__ B1s2_p,
    const float* __restrict__ lam1_p,
    const float* __restrict__ lam2_p,
    const float* __restrict__ logq_p,
    const float* __restrict__ logr_p,
    const float* __restrict__ gami_p,
    const float* __restrict__ gamc_p,
    int NT)
{
    extern __shared__ __align__(16) float buf[];         // [2 seg][2 par][SEGBUF] = 92.2 KB

    const int tid  = threadIdx.x;
    const int wid  = tid >> 5;                           // 0..3 -> SMSP 0..3
    const int lane = tid & 31;
    const int seg  = tid >> 6;                           // 0 = A, 1 = B
    const int s    = tid & 63;                           // series slot in CTA
    const int hw   = (tid >> 5) & 1;                     // warp-half within segment
    const int rowstride = NT * OBS;                      // 3600 floats
    const int NC = NT / CT;                              // 40 chunks

    const int c1A  = (NC * 21) / 40;                     // 21 (balanced 210/210)
    const int c0   = seg ? (c1A - 2) : 0;                // B: 2 warmup chunks (20 steps)
    const int c1   = seg ? NC : c1A;
    const int accC = seg ? c1A : 0;

    float* segbuf = buf + seg * (2 * SEGBUF);
    const float* ywarp = y + (size_t)(blockIdx.x * 64 + hw * 32) * rowstride;

    auto stage = [&](int ck, int b) {
        const float* s0 = ywarp + (size_t)ck * ROWF;
        unsigned d0 = su32(segbuf + b * SEGBUF + hw * 32 * ROWF);
#pragma unroll
        for (int p = 0; p < 2; ++p) {
            int cp2 = p * 32 + lane;                     // float2 col 0..44
            if (cp2 < ROWF / 2) {
                const float* sp = s0 + 2 * cp2;
                unsigned d = d0 + 8u * (unsigned)cp2;
#pragma unroll 4
                for (int i = 0; i < 32; ++i) {
                    asm volatile("cp.async.ca.shared.global [%0], [%1], 8;"
                                 :: "r"(d), "l"(sp));
                    sp += rowstride;
                    d += ROWF * 4;
                }
            }
        }
    };

    // ---------------- constants ----------------
    float B[3][3];
#pragma unroll
    for (int i = 0; i < 3; ++i)
#pragma unroll
        for (int j = 0; j < 3; ++j)
            B[i][j] = B1s1_p[i * 3 + j];
    const float b3 = B1s2_p[0];

    float q[4];
#pragma unroll
    for (int l = 0; l < 4; ++l) q[l] = expf(logq_p[l]);

    float c1v[9], c2v[9], dinv[9];
    c1v[0] = 1.f; c1v[1] = lam1_p[0]; c1v[2] = lam1_p[1];
    c1v[3] = 1.f; c1v[4] = lam1_p[2]; c1v[5] = lam1_p[3];
    c1v[6] = 1.f; c1v[7] = lam1_p[4]; c1v[8] = lam1_p[5];
    c2v[0] = 1.f;
#pragma unroll
    for (int o = 1; o < 9; ++o) c2v[o] = lam2_p[o - 1];

    float logdetD = 0.f;
    float a1[3] = {0.f, 0.f, 0.f};
    float a2 = 0.f;
#pragma unroll
    for (int o = 0; o < 9; ++o) {
        float r = expf(logr_p[o]);
        float d = r + 1e-6f;
        float di = 1.f / d;
        dinv[o] = di;
        logdetD += logf(d);
        a1[o / 3] += c1v[o] * c1v[o] * di;
        a2 += c2v[o] * c2v[o] * di;
    }
    const float CK = -0.5f * (9.f * LOG2PI_F + logdetD);
    const float g0 = gami_p[0];
    const float gc0 = gamc_p[0], gc1 = gamc_p[1], gc2 = gamc_p[2];

    // ---------------- state (standard prior at segment start) ----------------
    float P[4][4];
#pragma unroll
    for (int i = 0; i < 4; ++i)
#pragma unroll
        for (int j = 0; j < 4; ++j)
            P[i][j] = (i == j) ? 1000.f : 0.f;
    float eta[4] = {0.f, 0.f, 0.f, 0.f};
    float p1 = 0.99f, p2 = 0.01f;
    double ll = 0.0;

    stage(c0, c0 & 1);
    asm volatile("cp.async.commit_group;");

#pragma unroll 1
    for (int c = c0; c < c1; ++c) {
        if (c + 1 < c1) stage(c + 1, (c + 1) & 1);
        asm volatile("cp.async.commit_group;");
        asm volatile("cp.async.wait_group 1;");
        __syncwarp();

        const float* yb = segbuf + (c & 1) * SEGBUF + s * ROWF;
        const bool acc = (c >= accC);

#pragma unroll 1
        for (int st = 0; st < CT; ++st) {
            float yc[9];
#pragma unroll
            for (int o = 0; o < 9; ++o) yc[o] = yb[st * OBS + o];

            // ---- transition prob (pre-update eta) ----
            float lg = g0 + gc0 * eta[0] + gc1 * eta[1] + gc2 * eta[2];
            float p11 = __fdividef(1.f, 1.f + __expf(-lg));
            float p12 = 1.f - p11;

            // ---- predict ----
            float ep[4];
            ep[0] = B[0][0] * eta[0] + B[0][1] * eta[1] + B[0][2] * eta[2];
            ep[1] = B[1][0] * eta[0] + B[1][1] * eta[1] + B[1][2] * eta[2];
            ep[2] = B[2][0] * eta[0] + B[2][1] * eta[1] + B[2][2] * eta[2];
            ep[3] = b3 * eta[3];

            float T[4][4];
#pragma unroll
            for (int i = 0; i < 3; ++i)
#pragma unroll
                for (int j = 0; j < 4; ++j)
                    T[i][j] = B[i][0] * P[0][j] + B[i][1] * P[1][j] + B[i][2] * P[2][j];
#pragma unroll
            for (int j = 0; j < 4; ++j) T[3][j] = b3 * P[3][j];

            float Pp[4][4];
#pragma unroll
            for (int i = 0; i < 4; ++i) {
#pragma unroll
                for (int j = i; j < 4; ++j) {
                    float v = (j < 3)
                            ? T[i][0] * B[j][0] + T[i][1] * B[j][1] + T[i][2] * B[j][2]
                            : T[i][3] * b3;
                    Pp[i][j] = v; Pp[j][i] = v;
                }
            }
            Pp[0][0] += q[0]; Pp[1][1] += q[1]; Pp[2][2] += q[2]; Pp[3][3] += q[3];

            // ================= Regime 1: single-inverse Woodbury =================
            float m00 = Pp[0][0], m01 = Pp[0][1], m02 = Pp[0][2];
            float m11 = Pp[1][1], m12 = Pp[1][2], m22 = Pp[2][2];
            float S00 = 1.f + m00 * a1[0], S01 = m01 * a1[1], S02 = m02 * a1[2];
            float S10 = m01 * a1[0], S11 = 1.f + m11 * a1[1], S12 = m12 * a1[2];
            float S20 = m02 * a1[0], S21 = m12 * a1[1], S22 = 1.f + m22 * a1[2];

            float adj00 = S11 * S22 - S12 * S21;
            float adj01 = S02 * S21 - S01 * S22;
            float adj02 = S01 * S12 - S02 * S11;
            float adj10 = S12 * S20 - S10 * S22;
            float adj11 = S00 * S22 - S02 * S20;
            float adj12 = S02 * S10 - S00 * S12;
            float adj20 = S10 * S21 - S11 * S20;
            float adj21 = S01 * S20 - S00 * S21;
            float adj22 = S00 * S11 - S01 * S10;
            float detS = S00 * adj00 + S01 * adj10 + S02 * adj20;
            float idS = __fdividef(1.f, detS);

            float W00 = idS * (adj00 * m00 + adj01 * m01 + adj02 * m02);
            float W01 = idS * (adj00 * m01 + adj01 * m11 + adj02 * m12);
            float W02 = idS * (adj00 * m02 + adj01 * m12 + adj02 * m22);
            float W11 = idS * (adj10 * m01 + adj11 * m11 + adj12 * m12);
            float W12 = idS * (adj10 * m02 + adj11 * m12 + adj12 * m22);
            float W22 = idS * (adj20 * m02 + adj21 * m12 + adj22 * m22);

            float u0 = 0.f, u1 = 0.f, u2v = 0.f, quadD = 0.f;
#pragma unroll
            for (int o = 0; o < 9; ++o) {
                float v = yc[o] - c1v[o] * ep[o / 3];
                float sv = v * dinv[o];
                quadD += v * sv;
                float csv = c1v[o] * sv;
                if (o < 3) u0 += csv; else if (o < 6) u1 += csv; else u2v += csv;
            }
            float quad1 = quadD - (u0 * (W00 * u0 + W01 * u1 + W02 * u2v)
                                 + u1 * (W01 * u0 + W11 * u1 + W12 * u2v)
                                 + u2v * (W02 * u0 + W12 * u1 + W22 * u2v));
            float lp1 = -0.5f * (quad1 + __logf(detS)) + CK;

            float G00 = 1.f - a1[0] * W00, G01 = -a1[0] * W01, G02 = -a1[0] * W02;
            float G10 = -a1[1] * W01, G11 = 1.f - a1[1] * W11, G12 = -a1[1] * W12;
            float G20 = -a1[2] * W02, G21 = -a1[2] * W12, G22 = 1.f - a1[2] * W22;

            float K1s[4][3], Ka[4][3];
#pragma unroll
            for (int l = 0; l < 4; ++l) {
                K1s[l][0] = Pp[l][0] * G00 + Pp[l][1] * G10 + Pp[l][2] * G20;
                K1s[l][1] = Pp[l][0] * G01 + Pp[l][1] * G11 + Pp[l][2] * G21;
                K1s[l][2] = Pp[l][0] * G02 + Pp[l][1] * G12 + Pp[l][2] * G22;
                Ka[l][0] = K1s[l][0] * a1[0];
                Ka[l][1] = K1s[l][1] * a1[1];
                Ka[l][2] = K1s[l][2] * a1[2];
            }
            float eta1[4];
#pragma unroll
            for (int l = 0; l < 4; ++l)
                eta1[l] = ep[l] + K1s[l][0] * u0 + K1s[l][1] * u1 + K1s[l][2] * u2v;

            float P1u[10];
            {
                int idx = 0;
#pragma unroll
                for (int l = 0; l < 4; ++l)
#pragma unroll
                    for (int j = 0; j < 4; ++j)
                        if (j >= l)
                            P1u[idx++] = Pp[l][j] - Ka[l][0] * Pp[0][j]
                                                  - Ka[l][1] * Pp[1][j]
                                                  - Ka[l][2] * Pp[2][j];
            }

            // ================= Regime 2: rank-1 Sherman-Morrison =================
            float sP = Pp[3][3];
            float denom = 1.f + sP * a2;
            float iden = __fdividef(1.f, denom);
            float k2[4], ak[4];
#pragma unroll
            for (int l = 0; l < 4; ++l) { k2[l] = Pp[l][3] * iden; ak[l] = a2 * k2[l]; }

            float u2s = 0.f, quadD2 = 0.f;
#pragma unroll
            for (int o = 0; o < 9; ++o) {
                float v = yc[o] - c2v[o] * ep[3];
                float sv = v * dinv[o];
                quadD2 += v * sv;
                u2s += c2v[o] * sv;
            }
            float quad2 = quadD2 - sP * u2s * u2s * iden;
            float lp2 = -0.5f * (quad2 + __logf(denom)) + CK;

            float eta2[4];
#pragma unroll
            for (int l = 0; l < 4; ++l) eta2[l] = ep[l] + k2[l] * u2s;

            float P2u[10];
            {
                int idx = 0;
#pragma unroll
                for (int l = 0; l < 4; ++l)
#pragma unroll
                    for (int j = 0; j < 4; ++j)
                        if (j >= l)
                            P2u[idx++] = Pp[l][j] - ak[l] * Pp[3][j];
            }

            // ================= mixture collapse =================
            float lik1 = __expf(lp1);
            float lik2 = __expf(lp2);
            float num1 = lik1 * (p1 * p11);            // p21 = 0
            float num2 = lik2 * (p1 * p12 + p2);       // p22 = 1
            float marg = num1 + num2 + 1e-9f;
            float im = __fdividef(1.f, marg);
            float pt1 = num1 * im, pt2 = num2 * im;
            if (acc) ll += (double)__logf(marg);

            float dd1[4], dd2[4];
#pragma unroll
            for (int l = 0; l < 4; ++l) {
                float e = pt1 * eta1[l] + pt2 * eta2[l];
                dd1[l] = eta1[l] - e;
                dd2[l] = eta2[l] - e;
                eta[l] = e;
            }
            {
                int idx = 0;
#pragma unroll
                for (int l = 0; l < 4; ++l)
#pragma unroll
                    for (int j = 0; j < 4; ++j)
                        if (j >= l) {
                            float pn = pt1 * (P1u[idx] + dd1[l] * dd1[j])
                                     + pt2 * (P2u[idx] + dd2[l] * dd2[j]);
                            P[l][j] = pn; P[j][l] = pn;
                            ++idx;
                        }
            }
            p1 = pt1; p2 = pt2;
        }
    }

    // ---- per-CTA deterministic reduction -> partial ----
    double v = ll;
#pragma unroll
    for (int off = 16; off > 0; off >>= 1)
        v += __shfl_down_sync(0xffffffffu, v, off);

    __shared__ double wsum[TPB / 32];
    if (lane == 0) wsum[wid] = v;
    __syncthreads();

    __shared__ bool isLast;
    if (tid == 0) {
        g_partials[blockIdx.x] = (wsum[0] + wsum[1]) + (wsum[2] + wsum[3]);
        __threadfence();
        unsigned int done = atomicAdd(&g_done, 1u);
        isLast = (done == NBLK2 - 1);
    }
    __syncthreads();

    // ---- last CTA: fixed-order final reduction (deterministic) ----
    if (isLast) {
        __shared__ double sh[TPB];
        sh[tid] = g_partials[tid];                   // TPB == NBLK2 == 128
        __syncthreads();
        for (int k = TPB / 2; k > 0; k >>= 1) {
            if (tid < k) sh[tid] += sh[tid + k];
            __syncthreads();
        }
        if (tid == 0) {
            out[0] = (float)(-sh[0]);
            g_done = 0;                               // reset for next graph replay
        }
    }
}

extern "C" void kernel_launch(void* const* d_in, const int* in_sizes, int n_in,
                              void* d_out, int out_size)
{
    const float* y    = (const float*)d_in[0];
    const float* B1s1 = (const float*)d_in[1];
    const float* B1s2 = (const float*)d_in[2];
    const float* lam1 = (const float*)d_in[3];
    const float* lam2 = (const float*)d_in[4];
    const float* logq = (const float*)d_in[5];
    const float* logr = (const float*)d_in[6];
    const float* gami = (const float*)d_in[7];
    const float* gamc = (const float*)d_in[8];

    const int NT = in_sizes[0] / (NSER * OBS);   // 400 (divisible by CT=10)
    const int smem = 2 * 2 * SEGBUF * (int)sizeof(float);   // 92160 B

    static bool attr_set = false;
    if (!attr_set) {
        cudaFuncSetAttribute(kf_kernel,
                             cudaFuncAttributeMaxDynamicSharedMemorySize, smem);
        attr_set = true;
    }

    kf_kernel<<<NBLK2, TPB, smem>>>((float*)d_out, y, B1s1, B1s2, lam1, lam2,
                                    logq, logr, gami, gamc, NT);
}

// round 17
// speedup vs baseline: 1.1483x; 1.1483x over previous
#include <cuda_runtime.h>

#define NSER 8192
#define OBS 9
#define NBLK2 128             // CTAs; each runs FOUR time segments on 8 warps
#define TPB 256               // warp w -> SMSP w%4: every SMSP gets 2 warps
#define CT 10                 // timesteps per staged chunk
#define ROWF (CT * OBS)       // 90 floats; 90 mod 32 = 26, gcd 2 -> 2-way conflicts
#define SEGBUF (64 * ROWF)    // floats per (segment, parity) buffer
#define LOG2PI_F 1.8378770664093453f

static __device__ double g_partials[NBLK2];
static __device__ unsigned int g_done = 0;

__device__ __forceinline__ unsigned su32(const void* p) {
    unsigned a;
    asm("{ .reg .u64 t; cvta.to.shared.u64 t, %1; cvt.u32.u64 %0, t; }"
        : "=r"(a) : "l"(p));
    return a;
}

// 4-way time-split regime-switching KF.
// R15/R16 profiles: stalls are intra-warp dependency latency (issue 51-56%),
// so 2 warps/SMSP interleave beats 1 warp/SMSP. 256-thread CTAs put 2 warps on
// every SMSP of every SM (128 CTAs = 1/SM), and the 4-way time split cuts
// max steps/warp from 210 to 120 (20-step warmup per boundary).
//  seg0 (warps 0,1): chunks [0,12)  acc all        (t [0,120))
//  seg1 (warps 2,3): chunks [10,22) acc from 12    (t [100,220))
//  seg2 (warps 4,5): chunks [20,31) acc from 22    (t [200,310))
//  seg3 (warps 6,7): chunks [29,40) acc from 31    (t [290,400))
// Step math byte-identical to R9..R15. __launch_bounds__(TPB,1) pins regs
// (R16's spill to 96 regs came from ptxas chasing occupancy).
__global__ void __launch_bounds__(TPB, 1) kf_kernel(
    float* __restrict__ out,
    const float* __restrict__ y,
    const float* __restrict__ B1s1_p,
    const float* __restrict__ B1s2_p,
    const float* __restrict__ lam1_p,
    const float* __restrict__ lam2_p,
    const float* __restrict__ logq_p,
    const float* __restrict__ logr_p,
    const float* __restrict__ gami_p,
    const float* __restrict__ gamc_p,
    int NT)
{
    extern __shared__ __align__(16) float buf[];   // [4 seg][2 par][SEGBUF] = 184.3 KB

    const int tid  = threadIdx.x;
    const int wid  = tid >> 5;                     // 0..7 -> SMSP wid%4
    const int lane = tid & 31;
    const int seg  = wid >> 1;                     // 0..3
    const int hw   = wid & 1;                      // warp-half within segment
    const int s    = hw * 32 + lane;               // series slot 0..63 in CTA
    const int rowstride = NT * OBS;                // 3600 floats

    // chunk schedule (CT=10, NT=400, 2-chunk warmup, balanced 12/12/11/11)
    const int c0s_[4]  = {0, 10, 20, 29};
    const int c1s_[4]  = {12, 22, 31, 40};
    const int accs_[4] = {0, 12, 22, 31};
    const int c0   = c0s_[seg];
    const int c1   = c1s_[seg];
    const int accC = accs_[seg];

    float* segbuf = buf + seg * (2 * SEGBUF);
    const float* ywarp = y + (size_t)(blockIdx.x * 64 + hw * 32) * rowstride;

    auto stage = [&](int ck, int b) {
        const float* s0 = ywarp + (size_t)ck * ROWF;
        unsigned d0 = su32(segbuf + b * SEGBUF + hw * 32 * ROWF);
#pragma unroll
        for (int p = 0; p < 2; ++p) {
            int cp2 = p * 32 + lane;               // float2 col 0..44
            if (cp2 < ROWF / 2) {
                const float* sp = s0 + 2 * cp2;
                unsigned d = d0 + 8u * (unsigned)cp2;
#pragma unroll 4
                for (int i = 0; i < 32; ++i) {
                    asm volatile("cp.async.ca.shared.global [%0], [%1], 8;"
                                 :: "r"(d), "l"(sp));
                    sp += rowstride;
                    d += ROWF * 4;
                }
            }
        }
    };

    // ---------------- constants ----------------
    float B[3][3];
#pragma unroll
    for (int i = 0; i < 3; ++i)
#pragma unroll
        for (int j = 0; j < 3; ++j)
            B[i][j] = B1s1_p[i * 3 + j];
    const float b3 = B1s2_p[0];

    float q[4];
#pragma unroll
    for (int l = 0; l < 4; ++l) q[l] = expf(logq_p[l]);

    float c1v[9], c2v[9], dinv[9];
    c1v[0] = 1.f; c1v[1] = lam1_p[0]; c1v[2] = lam1_p[1];
    c1v[3] = 1.f; c1v[4] = lam1_p[2]; c1v[5] = lam1_p[3];
    c1v[6] = 1.f; c1v[7] = lam1_p[4]; c1v[8] = lam1_p[5];
    c2v[0] = 1.f;
#pragma unroll
    for (int o = 1; o < 9; ++o) c2v[o] = lam2_p[o - 1];

    float logdetD = 0.f;
    float a1[3] = {0.f, 0.f, 0.f};
    float a2 = 0.f;
#pragma unroll
    for (int o = 0; o < 9; ++o) {
        float r = expf(logr_p[o]);
        float d = r + 1e-6f;
        float di = 1.f / d;
        dinv[o] = di;
        logdetD += logf(d);
        a1[o / 3] += c1v[o] * c1v[o] * di;
        a2 += c2v[o] * c2v[o] * di;
    }
    const float CK = -0.5f * (9.f * LOG2PI_F + logdetD);
    const float g0 = gami_p[0];
    const float gc0 = gamc_p[0], gc1 = gamc_p[1], gc2 = gamc_p[2];

    // ---------------- state (standard prior at segment start) ----------------
    float P[4][4];
#pragma unroll
    for (int i = 0; i < 4; ++i)
#pragma unroll
        for (int j = 0; j < 4; ++j)
            P[i][j] = (i == j) ? 1000.f : 0.f;
    float eta[4] = {0.f, 0.f, 0.f, 0.f};
    float p1 = 0.99f, p2 = 0.01f;
    double ll = 0.0;

    stage(c0, c0 & 1);
    asm volatile("cp.async.commit_group;");

#pragma unroll 1
    for (int c = c0; c < c1; ++c) {
        if (c + 1 < c1) stage(c + 1, (c + 1) & 1);
        asm volatile("cp.async.commit_group;");
        asm volatile("cp.async.wait_group 1;");
        __syncwarp();

        const float* yb = segbuf + (c & 1) * SEGBUF + s * ROWF;
        const bool acc = (c >= accC);

#pragma unroll 1
        for (int st = 0; st < CT; ++st) {
            float yc[9];
#pragma unroll
            for (int o = 0; o < 9; ++o) yc[o] = yb[st * OBS + o];

            // ---- transition prob (pre-update eta) ----
            float lg = g0 + gc0 * eta[0] + gc1 * eta[1] + gc2 * eta[2];
            float p11 = __fdividef(1.f, 1.f + __expf(-lg));
            float p12 = 1.f - p11;

            // ---- predict ----
            float ep[4];
            ep[0] = B[0][0] * eta[0] + B[0][1] * eta[1] + B[0][2] * eta[2];
            ep[1] = B[1][0] * eta[0] + B[1][1] * eta[1] + B[1][2] * eta[2];
            ep[2] = B[2][0] * eta[0] + B[2][1] * eta[1] + B[2][2] * eta[2];
            ep[3] = b3 * eta[3];

            float T[4][4];
#pragma unroll
            for (int i = 0; i < 3; ++i)
#pragma unroll
                for (int j = 0; j < 4; ++j)
                    T[i][j] = B[i][0] * P[0][j] + B[i][1] * P[1][j] + B[i][2] * P[2][j];
#pragma unroll
            for (int j = 0; j < 4; ++j) T[3][j] = b3 * P[3][j];

            float Pp[4][4];
#pragma unroll
            for (int i = 0; i < 4; ++i) {
#pragma unroll
                for (int j = i; j < 4; ++j) {
                    float v = (j < 3)
                            ? T[i][0] * B[j][0] + T[i][1] * B[j][1] + T[i][2] * B[j][2]
                            : T[i][3] * b3;
                    Pp[i][j] = v; Pp[j][i] = v;
                }
            }
            Pp[0][0] += q[0]; Pp[1][1] += q[1]; Pp[2][2] += q[2]; Pp[3][3] += q[3];

            // ================= Regime 1: single-inverse Woodbury =================
            float m00 = Pp[0][0], m01 = Pp[0][1], m02 = Pp[0][2];
            float m11 = Pp[1][1], m12 = Pp[1][2], m22 = Pp[2][2];
            float S00 = 1.f + m00 * a1[0], S01 = m01 * a1[1], S02 = m02 * a1[2];
            float S10 = m01 * a1[0], S11 = 1.f + m11 * a1[1], S12 = m12 * a1[2];
            float S20 = m02 * a1[0], S21 = m12 * a1[1], S22 = 1.f + m22 * a1[2];

            float adj00 = S11 * S22 - S12 * S21;
            float adj01 = S02 * S21 - S01 * S22;
            float adj02 = S01 * S12 - S02 * S11;
            float adj10 = S12 * S20 - S10 * S22;
            float adj11 = S00 * S22 - S02 * S20;
            float adj12 = S02 * S10 - S00 * S12;
            float adj20 = S10 * S21 - S11 * S20;
            float adj21 = S01 * S20 - S00 * S21;
            float adj22 = S00 * S11 - S01 * S10;
            float detS = S00 * adj00 + S01 * adj10 + S02 * adj20;
            float idS = __fdividef(1.f, detS);

            float W00 = idS * (adj00 * m00 + adj01 * m01 + adj02 * m02);
            float W01 = idS * (adj00 * m01 + adj01 * m11 + adj02 * m12);
            float W02 = idS * (adj00 * m02 + adj01 * m12 + adj02 * m22);
            float W11 = idS * (adj10 * m01 + adj11 * m11 + adj12 * m12);
            float W12 = idS * (adj10 * m02 + adj11 * m12 + adj12 * m22);
            float W22 = idS * (adj20 * m02 + adj21 * m12 + adj22 * m22);

            float u0 = 0.f, u1 = 0.f, u2v = 0.f, quadD = 0.f;
#pragma unroll
            for (int o = 0; o < 9; ++o) {
                float v = yc[o] - c1v[o] * ep[o / 3];
                float sv = v * dinv[o];
                quadD += v * sv;
                float csv = c1v[o] * sv;
                if (o < 3) u0 += csv; else if (o < 6) u1 += csv; else u2v += csv;
            }
            float quad1 = quadD - (u0 * (W00 * u0 + W01 * u1 + W02 * u2v)
                                 + u1 * (W01 * u0 + W11 * u1 + W12 * u2v)
                                 + u2v * (W02 * u0 + W12 * u1 + W22 * u2v));
            float lp1 = -0.5f * (quad1 + __logf(detS)) + CK;

            float G00 = 1.f - a1[0] * W00, G01 = -a1[0] * W01, G02 = -a1[0] * W02;
            float G10 = -a1[1] * W01, G11 = 1.f - a1[1] * W11, G12 = -a1[1] * W12;
            float G20 = -a1[2] * W02, G21 = -a1[2] * W12, G22 = 1.f - a1[2] * W22;

            float K1s[4][3], Ka[4][3];
#pragma unroll
            for (int l = 0; l < 4; ++l) {
                K1s[l][0] = Pp[l][0] * G00 + Pp[l][1] * G10 + Pp[l][2] * G20;
                K1s[l][1] = Pp[l][0] * G01 + Pp[l][1] * G11 + Pp[l][2] * G21;
                K1s[l][2] = Pp[l][0] * G02 + Pp[l][1] * G12 + Pp[l][2] * G22;
                Ka[l][0] = K1s[l][0] * a1[0];
                Ka[l][1] = K1s[l][1] * a1[1];
                Ka[l][2] = K1s[l][2] * a1[2];
            }
            float eta1[4];
#pragma unroll
            for (int l = 0; l < 4; ++l)
                eta1[l] = ep[l] + K1s[l][0] * u0 + K1s[l][1] * u1 + K1s[l][2] * u2v;

            float P1u[10];
            {
                int idx = 0;
#pragma unroll
                for (int l = 0; l < 4; ++l)
#pragma unroll
                    for (int j = 0; j < 4; ++j)
                        if (j >= l)
                            P1u[idx++] = Pp[l][j] - Ka[l][0] * Pp[0][j]
                                                  - Ka[l][1] * Pp[1][j]
                                                  - Ka[l][2] * Pp[2][j];
            }

            // ================= Regime 2: rank-1 Sherman-Morrison =================
            float sP = Pp[3][3];
            float denom = 1.f + sP * a2;
            float iden = __fdividef(1.f, denom);
            float k2[4], ak[4];
#pragma unroll
            for (int l = 0; l < 4; ++l) { k2[l] = Pp[l][3] * iden; ak[l] = a2 * k2[l]; }

            float u2s = 0.f, quadD2 = 0.f;
#pragma unroll
            for (int o = 0; o < 9; ++o) {
                float v = yc[o] - c2v[o] * ep[3];
                float sv = v * dinv[o];
                quadD2 += v * sv;
                u2s += c2v[o] * sv;
            }
            float quad2 = quadD2 - sP * u2s * u2s * iden;
            float lp2 = -0.5f * (quad2 + __logf(denom)) + CK;

            float eta2[4];
#pragma unroll
            for (int l = 0; l < 4; ++l) eta2[l] = ep[l] + k2[l] * u2s;

            float P2u[10];
            {
                int idx = 0;
#pragma unroll
                for (int l = 0; l < 4; ++l)
#pragma unroll
                    for (int j = 0; j < 4; ++j)
                        if (j >= l)
                            P2u[idx++] = Pp[l][j] - ak[l] * Pp[3][j];
            }

            // ================= mixture collapse =================
            float lik1 = __expf(lp1);
            float lik2 = __expf(lp2);
            float num1 = lik1 * (p1 * p11);            // p21 = 0
            float num2 = lik2 * (p1 * p12 + p2);       // p22 = 1
            float marg = num1 + num2 + 1e-9f;
            float im = __fdividef(1.f, marg);
            float pt1 = num1 * im, pt2 = num2 * im;
            if (acc) ll += (double)__logf(marg);

            float dd1[4], dd2[4];
#pragma unroll
            for (int l = 0; l < 4; ++l) {
                float e = pt1 * eta1[l] + pt2 * eta2[l];
                dd1[l] = eta1[l] - e;
                dd2[l] = eta2[l] - e;
                eta[l] = e;
            }
            {
                int idx = 0;
#pragma unroll
                for (int l = 0; l < 4; ++l)
#pragma unroll
                    for (int j = 0; j < 4; ++j)
                        if (j >= l) {
                            float pn = pt1 * (P1u[idx] + dd1[l] * dd1[j])
                                     + pt2 * (P2u[idx] + dd2[l] * dd2[j]);
                            P[l][j] = pn; P[j][l] = pn;
                            ++idx;
                        }
            }
            p1 = pt1; p2 = pt2;
        }
    }

    // ---- per-CTA deterministic reduction -> partial ----
    double v = ll;
#pragma unroll
    for (int off = 16; off > 0; off >>= 1)
        v += __shfl_down_sync(0xffffffffu, v, off);

    __shared__ double wsum[TPB / 32];
    if (lane == 0) wsum[wid] = v;
    __syncthreads();

    __shared__ bool isLast;
    if (tid == 0) {
        double sacc = 0.0;
#pragma unroll
        for (int w = 0; w < TPB / 32; ++w) sacc += wsum[w];
        g_partials[blockIdx.x] = sacc;
        __threadfence();
        unsigned int done = atomicAdd(&g_done, 1u);
        isLast = (done == NBLK2 - 1);
    }
    __syncthreads();

    // ---- last CTA: fixed-order final reduction (deterministic) ----
    if (isLast) {
        __shared__ double sh[NBLK2];
        if (tid < NBLK2) sh[tid] = g_partials[tid];
        __syncthreads();
        for (int k = NBLK2 / 2; k > 0; k >>= 1) {
            if (tid < k) sh[tid] += sh[tid + k];
            __syncthreads();
        }
        if (tid == 0) {
            out[0] = (float)(-sh[0]);
            g_done = 0;                               // reset for next graph replay
        }
    }
}

extern "C" void kernel_launch(void* const* d_in, const int* in_sizes, int n_in,
                              void* d_out, int out_size)
{
    const float* y    = (const float*)d_in[0];
    const float* B1s1 = (const float*)d_in[1];
    const float* B1s2 = (const float*)d_in[2];
    const float* lam1 = (const float*)d_in[3];
    const float* lam2 = (const float*)d_in[4];
    const float* logq = (const float*)d_in[5];
    const float* logr = (const float*)d_in[6];
    const float* gami = (const float*)d_in[7];
    const float* gamc = (const float*)d_in[8];

    const int NT = in_sizes[0] / (NSER * OBS);   // 400 (divisible by CT=10)
    const int smem = 4 * 2 * SEGBUF * (int)sizeof(float);   // 184320 B

    static bool attr_set = false;
    if (!attr_set) {
        cudaFuncSetAttribute(kf_kernel,
                             cudaFuncAttributeMaxDynamicSharedMemorySize, smem);
        attr_set = true;
    }

    kf_kernel<<<NBLK2, TPB, smem>>>((float*)d_out, y, B1s1, B1s2, lam1, lam2,
                                    logq, logr, gami, gamc, NT);
}